// round 13
// baseline (speedup 1.0000x reference)
#include <cuda_runtime.h>
#include <cuda_bf16.h>
#include <cstdint>
#include <math.h>

#define Bb 128
#define Tt 512
#define Ee 256
#define Hh 128
#define FOURH 512
#define Vv 32000
#define KP 768

typedef unsigned long long u64t;
typedef __nv_bfloat16 bf16;

// ---------------- static scratch ----------------
__device__ float g_xw[(size_t)2 * Tt * Bb * FOURH];      // [dir][t*128+b][4H]
__device__ __align__(16) bf16 g_ehi[(size_t)Vv * Ee];
__device__ __align__(16) bf16 g_elo[(size_t)Vv * Ee];
__device__ __align__(16) bf16 g_Wt[2][KP][FOURH];        // [dir][k'][n]

// ---------------- helpers ----------------
__device__ __forceinline__ float sigmoid_f(float x) { return __fdividef(1.0f, 1.0f + __expf(-x)); }
__device__ __forceinline__ float tanh_f(float x)    { return __fdividef(2.0f, 1.0f + __expf(-2.0f * x)) - 1.0f; }
__device__ __forceinline__ uint32_t smem_u32(const void* p) {
    uint32_t a;
    asm("{ .reg .u64 t; cvta.to.shared.u64 t, %1; cvt.u32.u64 %0, t; }" : "=r"(a) : "l"(p));
    return a;
}
__device__ __forceinline__ void st_cluster_u32(uint32_t laddr, int rank, uint32_t v) {
    asm volatile(
        "{ .reg .b32 ra; mapa.shared::cluster.u32 ra, %0, %1; "
        "st.shared::cluster.b32 [ra], %2; }"
        :: "r"(laddr), "r"(rank), "r"(v) : "memory");
}
__device__ __forceinline__ void st_cluster_u16(uint32_t laddr, int rank, unsigned short v) {
    asm volatile(
        "{ .reg .b32 ra; mapa.shared::cluster.u32 ra, %0, %1; "
        "st.shared::cluster.b16 [ra], %2; }"
        :: "r"(laddr), "r"(rank), "h"(v) : "memory");
}
__device__ __forceinline__ void mbar_arrive_rel(uint32_t laddr, int rank) {
    asm volatile(
        "{ .reg .b32 ra; mapa.shared::cluster.u32 ra, %0, %1; "
        "mbarrier.arrive.release.cluster.shared::cluster.b64 _, [ra]; }"
        :: "r"(laddr), "r"(rank) : "memory");
}
__device__ __forceinline__ void mbar_wait_acq(uint32_t mb, uint32_t parity) {
    asm volatile(
        "{\n\t.reg .pred P1;\n\t"
        "WL_%=:\n\t"
        "mbarrier.try_wait.parity.acquire.cluster.shared::cta.b64 P1, [%0], %1, 0x989680;\n\t"
        "@P1 bra.uni WD_%=;\n\t"
        "bra.uni WL_%=;\n\t"
        "WD_%=:\n\t}" :: "r"(mb), "r"(parity) : "memory");
}
#define MBAR_INIT(a, n) \
    asm volatile("mbarrier.init.shared.b64 [%0], %1;" :: "r"(a), "r"((uint32_t)(n)) : "memory")
#define CLUSTER_SYNC() do { \
    asm volatile("barrier.cluster.arrive.aligned;" ::: "memory"); \
    asm volatile("barrier.cluster.wait.aligned;" ::: "memory"); \
} while (0)

#define LDSM_X4(r0, r1, r2, r3, addr) \
    asm volatile("ldmatrix.sync.aligned.m8n8.x4.shared.b16 {%0,%1,%2,%3}, [%4];" \
                 : "=r"(r0), "=r"(r1), "=r"(r2), "=r"(r3) : "r"(addr))
#define LDSM_X4T(r0, r1, r2, r3, addr) \
    asm volatile("ldmatrix.sync.aligned.m8n8.x4.trans.shared.b16 {%0,%1,%2,%3}, [%4];" \
                 : "=r"(r0), "=r"(r1), "=r"(r2), "=r"(r3) : "r"(addr))
#define MMA16816(c, a, b0, b1) \
    asm volatile("mma.sync.aligned.m16n8k16.row.col.f32.bf16.bf16.f32 " \
                 "{%0,%1,%2,%3}, {%4,%5,%6,%7}, {%8,%9}, {%0,%1,%2,%3};" \
                 : "+f"((c)[0]), "+f"((c)[1]), "+f"((c)[2]), "+f"((c)[3]) \
                 : "r"((a)[0]), "r"((a)[1]), "r"((a)[2]), "r"((a)[3]), "r"(b0), "r"(b1))

__device__ __forceinline__ unsigned short bfu(float x) {
    bf16 h = __float2bfloat16(x);
    return __bfloat16_as_ushort(h);
}
__device__ __forceinline__ float bff(unsigned short u) {
    return __bfloat162float(__ushort_as_bfloat16(u));
}

// ---------------- conversion kernels ----------------
__global__ void conv_emb(const float* __restrict__ emb) {
    size_t i = (size_t)blockIdx.x * 256 + threadIdx.x;
    if (i < (size_t)Vv * Ee) {
        float x = emb[i];
        bf16 h = __float2bfloat16(x);
        g_ehi[i] = h;
        g_elo[i] = __float2bfloat16(x - __bfloat162float(h));
    }
}
__global__ void conv_w(const float* __restrict__ Wfw, const float* __restrict__ Wbw) {
    int i = blockIdx.x * 256 + threadIdx.x;
    if (i < 2 * KP * FOURH) {
        int d  = i / (KP * FOURH);
        int r  = i % (KP * FOURH);
        int kp = r / FOURH, n = r % FOURH;
        const float* W = d ? Wbw : Wfw;
        float x = W[(size_t)(kp & 255) * FOURH + n];
        bf16 hv = __float2bfloat16(x);
        g_Wt[d][kp][n] = (kp >= 256 && kp < 512)
                             ? __float2bfloat16(x - __bfloat162float(hv)) : hv;
    }
}

// ---------------- mma.sync projection GEMM (unchanged) ----------------
#define ASTR 40
#define BSTR 136

__global__ __launch_bounds__(256)
void proj_mma(const int* __restrict__ tokens) {
    __shared__ __align__(16) bf16 A_sm[128 * ASTR];
    __shared__ __align__(16) bf16 B_sm[32 * BSTR];
    __shared__ int tok[128];

    const int tid = threadIdx.x;
    const int wid = tid >> 5, lane = tid & 31;
    const int wm = wid & 3, wn = wid >> 2;
    const int n0 = blockIdx.x * 128;
    const int m0 = blockIdx.y * 128;
    const int dir = blockIdx.z;

    if (tid < 128) {
        int row = m0 + tid;
        tok[tid] = tokens[(row & 127) * Tt + (row >> 7)];
    }
    const uint32_t sbA = smem_u32(A_sm);
    const uint32_t sbB = smem_u32(B_sm);

    float c[2][8][4];
#pragma unroll
    for (int i = 0; i < 2; i++)
#pragma unroll
        for (int j = 0; j < 8; j++)
#pragma unroll
            for (int q = 0; q < 4; q++) c[i][j][q] = 0.0f;

    __syncthreads();

    for (int kt = 0; kt < 24; kt++) {
        const int kp0 = kt * 32;
        const bf16* __restrict__ Asrc = (kp0 < 512) ? g_ehi : g_elo;
        const int kb = kp0 & 255;

        uint4 av[2], bv[2];
#pragma unroll
        for (int u = 0; u < 2; u++) {
            const int q = tid + u * 256;
            const int arow = q >> 2, ac8 = q & 3;
            av[u] = *(const uint4*)(Asrc + (size_t)tok[arow] * Ee + kb + ac8 * 8);
            const int brow = q >> 4, bn8 = q & 15;
            bv[u] = *(const uint4*)(&g_Wt[dir][kp0 + brow][n0 + bn8 * 8]);
        }
        __syncthreads();
#pragma unroll
        for (int u = 0; u < 2; u++) {
            const int q = tid + u * 256;
            const int arow = q >> 2, ac8 = q & 3;
            *(uint4*)(A_sm + arow * ASTR + ac8 * 8) = av[u];
            const int brow = q >> 4, bn8 = q & 15;
            *(uint4*)(B_sm + brow * BSTR + bn8 * 8) = bv[u];
        }
        __syncthreads();

#pragma unroll
        for (int ks = 0; ks < 2; ks++) {
            uint32_t a[2][4];
#pragma unroll
            for (int i = 0; i < 2; i++) {
                const int m = wm * 32 + i * 16 + (lane & 7) + ((lane >> 3) & 1) * 8;
                const int kc = ks * 16 + (lane >> 4) * 8;
                LDSM_X4(a[i][0], a[i][1], a[i][2], a[i][3],
                        sbA + (uint32_t)(m * ASTR + kc) * 2);
            }
            uint32_t b[4][4];
#pragma unroll
            for (int j2 = 0; j2 < 4; j2++) {
                const int k = ks * 16 + (lane & 7) + ((lane >> 3) & 1) * 8;
                const int n = wn * 64 + j2 * 16 + (lane >> 4) * 8;
                LDSM_X4T(b[j2][0], b[j2][1], b[j2][2], b[j2][3],
                         sbB + (uint32_t)(k * BSTR + n) * 2);
            }
#pragma unroll
            for (int i = 0; i < 2; i++)
#pragma unroll
                for (int j = 0; j < 8; j++)
                    MMA16816(c[i][j], a[i], b[j >> 1][(j & 1) * 2], b[j >> 1][(j & 1) * 2 + 1]);
        }
    }

    const int g = lane >> 2, t2 = (lane & 3) * 2;
    float* const base = g_xw + (size_t)dir * Tt * Bb * FOURH;
#pragma unroll
    for (int i = 0; i < 2; i++) {
        const int mrow = m0 + wm * 32 + i * 16 + g;
#pragma unroll
        for (int j = 0; j < 8; j++) {
            const int col = n0 + wn * 64 + j * 8 + t2;
            float* d0 = base + (size_t)mrow * FOURH + col;
            d0[0] = c[i][j][0]; d0[1] = c[i][j][1];
            float* d1 = d0 + 8 * FOURH;
            d1[0] = c[i][j][2]; d1[1] = c[i][j][3];
        }
    }
}

// ---------------- persistent LSTM: 2 interleaved groups per CTA ----------------
// 64 CTAs, cluster(4). bx = dir*32 + pair*4 + utile. Group A = btile `pair`,
// group B = btile `pair+8` (same dir/utile -> SAME U register fragments).
// Per step: compute+publish A, compute+publish B; per-(group,parity)
// mbarriers (count=4) replace the cluster barrier; each group's sync
// round-trip is hidden behind the other group's compute.
#define HSTR 784              // A row stride bytes (768 data + 16 pad)
#define NKS 24                // K' = 384 -> 24 k16 steps
#define HBUFSZ (16 * HSTR)    // one parity buffer: 12544 B
#define ZOFF   64
#define HAOFF  (ZOFF + 8 * 132 * 4)          // 4288
#define HBOFF  (HAOFF + 2 * HBUFSZ)          // 29376
#define LSTM_SMEM (HBOFF + 2 * HBUFSZ)       // 54464

__global__ __launch_bounds__(256, 1) __cluster_dims__(4, 1, 1)
void lstm_kernel(const float* __restrict__ Ufw, const float* __restrict__ Ubw,
                 const float* __restrict__ bfw, const float* __restrict__ bbw,
                 float* __restrict__ out) {
    extern __shared__ char sm[];
    float (*z_sm)[132] = (float(*)[132])(sm + ZOFF);
    const uint32_t sbase = smem_u32(sm);

    const int bx = blockIdx.x;
    const int dir = bx >> 5;
    const int pair = (bx >> 2) & 7;
    const int utile = bx & 3;
    const int tid = threadIdx.x;
    const int w = tid >> 5, lane = tid & 31;
    const int kq = lane & 3, nq = lane >> 2;
    const int ju = tid >> 3, bl = tid & 7;
    const int j = utile * 32 + ju;          // global unit 0..127

    const float* __restrict__ U    = dir ? Ubw : Ufw;
    const float* __restrict__ bias = dir ? bbw : bfw;

    // ---- U fragments in registers (shared by both groups) ----
    uint32_t breg[NKS][2][2];
#pragma unroll
    for (int tile = 0; tile < 2; tile++) {
        const int nloc = w * 16 + tile * 8 + nq;
        const int gcol = (nloc >> 5) * Hh + utile * 32 + (nloc & 31);
#pragma unroll
        for (int ks = 0; ks < 16; ks++) {
            const int u0 = 8 * ks + kq;
            const unsigned short h0 = bfu(U[(size_t)u0 * FOURH + gcol]);
            const unsigned short h1 = bfu(U[(size_t)(u0 + 4) * FOURH + gcol]);
            breg[ks][tile][0] = (uint32_t)h0 | ((uint32_t)h0 << 16);
            breg[ks][tile][1] = (uint32_t)h1 | ((uint32_t)h1 << 16);
        }
#pragma unroll
        for (int ks = 16; ks < NKS; ks++) {
            const int u0 = 16 * (ks - 16) + 2 * kq;
#pragma unroll
            for (int rr = 0; rr < 2; rr++) {
                const int ua = u0 + rr * 8, ub = ua + 1;
                float va = U[(size_t)ua * FOURH + gcol];
                float vb = U[(size_t)ub * FOURH + gcol];
                unsigned short la = bfu(va - bff(bfu(va)));
                unsigned short lb = bfu(vb - bff(bfu(vb)));
                breg[ks][tile][rr] = (uint32_t)la | ((uint32_t)lb << 16);
            }
        }
    }

    // zero both groups' h buffers; init 4 mbarriers (count=4)
    for (int q = tid; q < (HBOFF + 2 * HBUFSZ - HAOFF) / 4; q += 256)
        ((uint32_t*)(sm + HAOFF))[q] = 0u;
    if (tid == 0)
#pragma unroll
        for (int m = 0; m < 4; m++) MBAR_INIT(sbase + m * 8, 4);

    const float bz0 = bias[j];
    const float bz1 = bias[Hh + j];
    const float bz2 = bias[2 * Hh + j];
    const float bz3 = bias[3 * Hh + j];

    __syncthreads();
    CLUSTER_SYNC();   // peers' mbars + zeroed buffers visible

    const int arow = (lane & 7) + ((lane >> 3) & 1) * 8;
    const uint32_t rowoff = (uint32_t)(arow * HSTR + (lane >> 4) * 16);
    const uint32_t hoff32 = (uint32_t)(bl * HSTR + j * 4);
    const uint32_t hoff16 = (uint32_t)(bl * HSTR + 512 + j * 2);

    float cst0 = 0.0f, cst1 = 0.0f, hout0 = 0.0f, hout1 = 0.0f;
    const size_t xw_dir = (size_t)dir * ((size_t)Tt * Bb * FOURH);

    for (int t = 0; t < Tt; t++) {
        const int tt = dir ? (Tt - 1 - t) : t;
        const int p = t & 1;
        // wait phase for mbar[g][p] at step t: p ? ((t>>1)&1) : (((t>>1)-1)&1)
        const uint32_t wph = p ? ((uint32_t)(t >> 1) & 1u)
                               : (((uint32_t)(t >> 1) - 1u) & 1u);

        // prefetch xw for both groups before any wait
        float xg[2][4];
#pragma unroll
        for (int g = 0; g < 2; g++) {
            const int b = (pair + g * 8) * 8 + bl;
            const float* xwp = g_xw + xw_dir + ((size_t)tt * Bb + b) * FOURH;
            xg[g][0] = __ldg(xwp + j);
            xg[g][1] = __ldg(xwp + Hh + j);
            xg[g][2] = __ldg(xwp + 2 * Hh + j);
            xg[g][3] = __ldg(xwp + 3 * Hh + j);
        }

#pragma unroll
        for (int g = 0; g < 2; g++) {
            const uint32_t hb = sbase + (g ? HBOFF : HAOFF);
            const uint32_t mb_rd = sbase + (uint32_t)((g * 2 + p) * 8);
            const uint32_t mb_wr = sbase + (uint32_t)((g * 2 + (p ^ 1)) * 8);

            if (t > 0) mbar_wait_acq(mb_rd, wph);

            // z = h @ U
            float cA[2][4], cB[2][4];
#pragma unroll
            for (int i = 0; i < 2; i++)
#pragma unroll
                for (int q = 0; q < 4; q++) { cA[i][q] = 0.0f; cB[i][q] = 0.0f; }

            const uint32_t abase = hb + (uint32_t)(p * HBUFSZ) + rowoff;
#pragma unroll
            for (int ks = 0; ks < NKS; ks++) {
                uint32_t a[4];
                LDSM_X4(a[0], a[1], a[2], a[3], abase + (uint32_t)(32 * ks));
                if (ks & 1) {
                    MMA16816(cB[0], a, breg[ks][0][0], breg[ks][0][1]);
                    MMA16816(cB[1], a, breg[ks][1][0], breg[ks][1][1]);
                } else {
                    MMA16816(cA[0], a, breg[ks][0][0], breg[ks][0][1]);
                    MMA16816(cA[1], a, breg[ks][1][0], breg[ks][1][1]);
                }
            }
            *(float2*)&z_sm[nq][w * 16 + 2 * kq] =
                make_float2(cA[0][0] + cB[0][0], cA[0][1] + cB[0][1]);
            *(float2*)&z_sm[nq][w * 16 + 8 + 2 * kq] =
                make_float2(cA[1][0] + cB[1][0], cA[1][1] + cB[1][1]);
            __syncthreads();

            float& cst  = g ? cst1 : cst0;
            float& hout = g ? hout1 : hout0;
            const float a0 = z_sm[bl][ju]      + xg[g][0] + bz0;
            const float a1 = z_sm[bl][32 + ju] + xg[g][1] + bz1;
            const float a2 = z_sm[bl][64 + ju] + xg[g][2] + bz2;
            const float a3 = z_sm[bl][96 + ju] + xg[g][3] + bz3;
            {
                const float ig = sigmoid_f(a0), fg = sigmoid_f(a1);
                const float gg = tanh_f(a2),    og = sigmoid_f(a3);
                cst = fg * cst + ig * gg;
                hout = og * tanh_f(cst);
            }

            // publish h into buffer p^1 of all 4 cluster CTAs
            {
                const unsigned short hh = bfu(hout);
                const unsigned short hl = bfu(hout - bff(hh));
                const uint32_t v32 = (uint32_t)hh | ((uint32_t)hl << 16);
                const uint32_t base = hb + (uint32_t)((p ^ 1) * HBUFSZ);
#pragma unroll
                for (int r = 0; r < 4; r++) {
                    st_cluster_u32(base + hoff32, r, v32);
                    st_cluster_u16(base + hoff16, r, hh);
                }
            }
            __syncthreads();           // stores ordered + z_sm safe for reuse
            if (tid < 4) mbar_arrive_rel(mb_wr, tid);

            // out store in the shadow of the sync propagation
            const int b = (pair + g * 8) * 8 + bl;
            out[((size_t)b * Tt + tt) * 256 + dir * Hh + j] = hout;
        }
    }

    const size_t fin = (size_t)Bb * Tt * 256 + (size_t)dir * 2 * Bb * Hh;
#pragma unroll
    for (int g = 0; g < 2; g++) {
        const int b = (pair + g * 8) * 8 + bl;
        out[fin + (size_t)b * Hh + j]           = g ? hout1 : hout0;
        out[fin + Bb * Hh + (size_t)b * Hh + j] = g ? cst1 : cst0;
    }

    CLUSTER_SYNC();   // keep smem alive until all peers stop DSMEM-writing
}

// ---------------- launch ----------------
extern "C" void kernel_launch(void* const* d_in, const int* in_sizes, int n_in,
                              void* d_out, int out_size) {
    const int*   tokens = (const int*)d_in[0];
    const float* emb    = (const float*)d_in[1];
    const float* Wfw    = (const float*)d_in[2];
    const float* Ufw    = (const float*)d_in[3];
    const float* bfw    = (const float*)d_in[4];
    const float* Wbw    = (const float*)d_in[5];
    const float* Ubw    = (const float*)d_in[6];
    const float* bbw    = (const float*)d_in[7];
    float* out = (float*)d_out;

    static bool attr_set = false;
    if (!attr_set) {
        cudaFuncSetAttribute(lstm_kernel, cudaFuncAttributeMaxDynamicSharedMemorySize,
                             (int)LSTM_SMEM);
        attr_set = true;
    }

    conv_emb<<<(Vv * Ee + 255) / 256, 256>>>(emb);
    conv_w<<<(2 * KP * FOURH + 255) / 256, 256>>>(Wfw, Wbw);
    proj_mma<<<dim3(4, 512, 2), 256>>>(tokens);
    lstm_kernel<<<64, 256, LSTM_SMEM>>>(Ufw, Ubw, bfw, bbw, out);
}

// round 14
// speedup vs baseline: 1.2415x; 1.2415x over previous
#include <cuda_runtime.h>
#include <cuda_bf16.h>
#include <cstdint>
#include <math.h>

#define Bb 128
#define Tt 512
#define Ee 256
#define Hh 128
#define FOURH 512
#define Vv 32000
#define KP 768

typedef unsigned long long u64t;
typedef __nv_bfloat16 bf16;

// ---------------- static scratch ----------------
__device__ float g_xw[(size_t)2 * Tt * Bb * FOURH];      // [dir][t*128+b][4H]
__device__ __align__(16) bf16 g_ehi[(size_t)Vv * Ee];
__device__ __align__(16) bf16 g_elo[(size_t)Vv * Ee];
__device__ __align__(16) bf16 g_Wt[2][KP][FOURH];        // [dir][k'][n]

// ---------------- helpers ----------------
__device__ __forceinline__ float sigmoid_f(float x) { return __fdividef(1.0f, 1.0f + __expf(-x)); }
__device__ __forceinline__ float tanh_f(float x)    { return __fdividef(2.0f, 1.0f + __expf(-2.0f * x)) - 1.0f; }
__device__ __forceinline__ uint32_t smem_u32(const void* p) {
    uint32_t a;
    asm("{ .reg .u64 t; cvta.to.shared.u64 t, %1; cvt.u32.u64 %0, t; }" : "=r"(a) : "l"(p));
    return a;
}
__device__ __forceinline__ void st_cluster_u32(uint32_t laddr, int rank, uint32_t v) {
    asm volatile(
        "{ .reg .b32 ra; mapa.shared::cluster.u32 ra, %0, %1; "
        "st.shared::cluster.b32 [ra], %2; }"
        :: "r"(laddr), "r"(rank), "r"(v) : "memory");
}
__device__ __forceinline__ void st_cluster_u16(uint32_t laddr, int rank, unsigned short v) {
    asm volatile(
        "{ .reg .b32 ra; mapa.shared::cluster.u32 ra, %0, %1; "
        "st.shared::cluster.b16 [ra], %2; }"
        :: "r"(laddr), "r"(rank), "h"(v) : "memory");
}
__device__ __forceinline__ void mbar_arrive_rel(uint32_t laddr, int rank) {
    asm volatile(
        "{ .reg .b32 ra; mapa.shared::cluster.u32 ra, %0, %1; "
        "mbarrier.arrive.release.cluster.shared::cluster.b64 _, [ra]; }"
        :: "r"(laddr), "r"(rank) : "memory");
}
__device__ __forceinline__ void mbar_wait_acq(uint32_t mb, uint32_t parity) {
    asm volatile(
        "{\n\t.reg .pred P1;\n\t"
        "WL_%=:\n\t"
        "mbarrier.try_wait.parity.acquire.cluster.shared::cta.b64 P1, [%0], %1, 0x989680;\n\t"
        "@P1 bra.uni WD_%=;\n\t"
        "bra.uni WL_%=;\n\t"
        "WD_%=:\n\t}" :: "r"(mb), "r"(parity) : "memory");
}
#define MBAR_INIT(a, n) \
    asm volatile("mbarrier.init.shared.b64 [%0], %1;" :: "r"(a), "r"((uint32_t)(n)) : "memory")
#define CLUSTER_SYNC() do { \
    asm volatile("barrier.cluster.arrive.aligned;" ::: "memory"); \
    asm volatile("barrier.cluster.wait.aligned;" ::: "memory"); \
} while (0)

#define LDSM_X4(r0, r1, r2, r3, addr) \
    asm volatile("ldmatrix.sync.aligned.m8n8.x4.shared.b16 {%0,%1,%2,%3}, [%4];" \
                 : "=r"(r0), "=r"(r1), "=r"(r2), "=r"(r3) : "r"(addr))
#define LDSM_X4T(r0, r1, r2, r3, addr) \
    asm volatile("ldmatrix.sync.aligned.m8n8.x4.trans.shared.b16 {%0,%1,%2,%3}, [%4];" \
                 : "=r"(r0), "=r"(r1), "=r"(r2), "=r"(r3) : "r"(addr))
#define MMA16816(c, a, b0, b1) \
    asm volatile("mma.sync.aligned.m16n8k16.row.col.f32.bf16.bf16.f32 " \
                 "{%0,%1,%2,%3}, {%4,%5,%6,%7}, {%8,%9}, {%0,%1,%2,%3};" \
                 : "+f"((c)[0]), "+f"((c)[1]), "+f"((c)[2]), "+f"((c)[3]) \
                 : "r"((a)[0]), "r"((a)[1]), "r"((a)[2]), "r"((a)[3]), "r"(b0), "r"(b1))

__device__ __forceinline__ unsigned short bfu(float x) {
    bf16 h = __float2bfloat16(x);
    return __bfloat16_as_ushort(h);
}
__device__ __forceinline__ float bff(unsigned short u) {
    return __bfloat162float(__ushort_as_bfloat16(u));
}

// ---------------- conversion kernels ----------------
__global__ void conv_emb(const float* __restrict__ emb) {
    size_t i = (size_t)blockIdx.x * 256 + threadIdx.x;
    if (i < (size_t)Vv * Ee) {
        float x = emb[i];
        bf16 h = __float2bfloat16(x);
        g_ehi[i] = h;
        g_elo[i] = __float2bfloat16(x - __bfloat162float(h));
    }
}
__global__ void conv_w(const float* __restrict__ Wfw, const float* __restrict__ Wbw) {
    int i = blockIdx.x * 256 + threadIdx.x;
    if (i < 2 * KP * FOURH) {
        int d  = i / (KP * FOURH);
        int r  = i % (KP * FOURH);
        int kp = r / FOURH, n = r % FOURH;
        const float* W = d ? Wbw : Wfw;
        float x = W[(size_t)(kp & 255) * FOURH + n];
        bf16 hv = __float2bfloat16(x);
        g_Wt[d][kp][n] = (kp >= 256 && kp < 512)
                             ? __float2bfloat16(x - __bfloat162float(hv)) : hv;
    }
}

// ---------------- mma.sync projection GEMM (unchanged) ----------------
#define ASTR 40
#define BSTR 136

__global__ __launch_bounds__(256)
void proj_mma(const int* __restrict__ tokens) {
    __shared__ __align__(16) bf16 A_sm[128 * ASTR];
    __shared__ __align__(16) bf16 B_sm[32 * BSTR];
    __shared__ int tok[128];

    const int tid = threadIdx.x;
    const int wid = tid >> 5, lane = tid & 31;
    const int wm = wid & 3, wn = wid >> 2;
    const int n0 = blockIdx.x * 128;
    const int m0 = blockIdx.y * 128;
    const int dir = blockIdx.z;

    if (tid < 128) {
        int row = m0 + tid;
        tok[tid] = tokens[(row & 127) * Tt + (row >> 7)];
    }
    const uint32_t sbA = smem_u32(A_sm);
    const uint32_t sbB = smem_u32(B_sm);

    float c[2][8][4];
#pragma unroll
    for (int i = 0; i < 2; i++)
#pragma unroll
        for (int j = 0; j < 8; j++)
#pragma unroll
            for (int q = 0; q < 4; q++) c[i][j][q] = 0.0f;

    __syncthreads();

    for (int kt = 0; kt < 24; kt++) {
        const int kp0 = kt * 32;
        const bf16* __restrict__ Asrc = (kp0 < 512) ? g_ehi : g_elo;
        const int kb = kp0 & 255;

        uint4 av[2], bv[2];
#pragma unroll
        for (int u = 0; u < 2; u++) {
            const int q = tid + u * 256;
            const int arow = q >> 2, ac8 = q & 3;
            av[u] = *(const uint4*)(Asrc + (size_t)tok[arow] * Ee + kb + ac8 * 8);
            const int brow = q >> 4, bn8 = q & 15;
            bv[u] = *(const uint4*)(&g_Wt[dir][kp0 + brow][n0 + bn8 * 8]);
        }
        __syncthreads();
#pragma unroll
        for (int u = 0; u < 2; u++) {
            const int q = tid + u * 256;
            const int arow = q >> 2, ac8 = q & 3;
            *(uint4*)(A_sm + arow * ASTR + ac8 * 8) = av[u];
            const int brow = q >> 4, bn8 = q & 15;
            *(uint4*)(B_sm + brow * BSTR + bn8 * 8) = bv[u];
        }
        __syncthreads();

#pragma unroll
        for (int ks = 0; ks < 2; ks++) {
            uint32_t a[2][4];
#pragma unroll
            for (int i = 0; i < 2; i++) {
                const int m = wm * 32 + i * 16 + (lane & 7) + ((lane >> 3) & 1) * 8;
                const int kc = ks * 16 + (lane >> 4) * 8;
                LDSM_X4(a[i][0], a[i][1], a[i][2], a[i][3],
                        sbA + (uint32_t)(m * ASTR + kc) * 2);
            }
            uint32_t b[4][4];
#pragma unroll
            for (int j2 = 0; j2 < 4; j2++) {
                const int k = ks * 16 + (lane & 7) + ((lane >> 3) & 1) * 8;
                const int n = wn * 64 + j2 * 16 + (lane >> 4) * 8;
                LDSM_X4T(b[j2][0], b[j2][1], b[j2][2], b[j2][3],
                         sbB + (uint32_t)(k * BSTR + n) * 2);
            }
#pragma unroll
            for (int i = 0; i < 2; i++)
#pragma unroll
                for (int j = 0; j < 8; j++)
                    MMA16816(c[i][j], a[i], b[j >> 1][(j & 1) * 2], b[j >> 1][(j & 1) * 2 + 1]);
        }
    }

    const int g = lane >> 2, t2 = (lane & 3) * 2;
    float* const base = g_xw + (size_t)dir * Tt * Bb * FOURH;
#pragma unroll
    for (int i = 0; i < 2; i++) {
        const int mrow = m0 + wm * 32 + i * 16 + g;
#pragma unroll
        for (int j = 0; j < 8; j++) {
            const int col = n0 + wn * 64 + j * 8 + t2;
            float* d0 = base + (size_t)mrow * FOURH + col;
            d0[0] = c[i][j][0]; d0[1] = c[i][j][1];
            float* d1 = d0 + 8 * FOURH;
            d1[0] = c[i][j][2]; d1[1] = c[i][j][3];
        }
    }
}

// ---------------- persistent LSTM: R12 structure + mbarrier sync ----------------
// 128 CTAs, cluster(4) = one (dir,btile). CTA: 8 batch rows x 32 units.
// Per step: z = h_pad[16,384] @ Ureg[384,128] via mma.sync, U in registers.
// h via DSMEM; per-parity mbarriers (count=4) replace barrier.cluster.
#define HSTR 784              // A row stride bytes (768 data + 16 pad)
#define NKS 24                // K' = 384 -> 24 k16 steps
#define HBUFSZ (16 * HSTR)
#define ZOFF   64
#define HOFF   (ZOFF + 8 * 132 * 4)          // 4288
#define LSTM_SMEM (HOFF + 2 * HBUFSZ)        // 29376

__global__ __launch_bounds__(256, 1) __cluster_dims__(4, 1, 1)
void lstm_kernel(const float* __restrict__ Ufw, const float* __restrict__ Ubw,
                 const float* __restrict__ bfw, const float* __restrict__ bbw,
                 float* __restrict__ out) {
    extern __shared__ char sm[];
    float (*z_sm)[132] = (float(*)[132])(sm + ZOFF);
    const uint32_t sbase = smem_u32(sm);
    const uint32_t hb = sbase + HOFF;

    const int bx = blockIdx.x;
    const int dir = bx >> 6, id = bx & 63;
    const int btile = id >> 2, utile = id & 3;
    const int tid = threadIdx.x;
    const int w = tid >> 5, lane = tid & 31;
    const int kq = lane & 3, nq = lane >> 2;
    const int ju = tid >> 3, bl = tid & 7;
    const int j = utile * 32 + ju;          // global unit 0..127
    const int b = btile * 8 + bl;           // global batch row

    const float* __restrict__ U    = dir ? Ubw : Ufw;
    const float* __restrict__ bias = dir ? bbw : bfw;

    // ---- U fragments in registers ----
    uint32_t breg[NKS][2][2];
#pragma unroll
    for (int tile = 0; tile < 2; tile++) {
        const int nloc = w * 16 + tile * 8 + nq;
        const int gcol = (nloc >> 5) * Hh + utile * 32 + (nloc & 31);
#pragma unroll
        for (int ks = 0; ks < 16; ks++) {      // (hhi,hlo) x dup(Uhi)
            const int u0 = 8 * ks + kq;
            const unsigned short h0 = bfu(U[(size_t)u0 * FOURH + gcol]);
            const unsigned short h1 = bfu(U[(size_t)(u0 + 4) * FOURH + gcol]);
            breg[ks][tile][0] = (uint32_t)h0 | ((uint32_t)h0 << 16);
            breg[ks][tile][1] = (uint32_t)h1 | ((uint32_t)h1 << 16);
        }
#pragma unroll
        for (int ks = 16; ks < NKS; ks++) {    // hhi x Ulo
            const int u0 = 16 * (ks - 16) + 2 * kq;
#pragma unroll
            for (int rr = 0; rr < 2; rr++) {
                const int ua = u0 + rr * 8, ub = ua + 1;
                float va = U[(size_t)ua * FOURH + gcol];
                float vb = U[(size_t)ub * FOURH + gcol];
                unsigned short la = bfu(va - bff(bfu(va)));
                unsigned short lb = bfu(vb - bff(bfu(vb)));
                breg[ks][tile][rr] = (uint32_t)la | ((uint32_t)lb << 16);
            }
        }
    }

    // zero both h buffers; init 2 per-parity mbarriers (count=4)
    for (int q = tid; q < (int)(2 * HBUFSZ / 4); q += 256)
        ((uint32_t*)(sm + HOFF))[q] = 0u;
    if (tid == 0) { MBAR_INIT(sbase, 4); MBAR_INIT(sbase + 8, 4); }

    const float bz0 = bias[j];
    const float bz1 = bias[Hh + j];
    const float bz2 = bias[2 * Hh + j];
    const float bz3 = bias[3 * Hh + j];

    __syncthreads();
    CLUSTER_SYNC();   // peers' mbars + zeroed buffers visible

    const int arow = (lane & 7) + ((lane >> 3) & 1) * 8;
    const uint32_t rowoff = (uint32_t)(arow * HSTR + (lane >> 4) * 16);
    const uint32_t hoff32 = (uint32_t)(bl * HSTR + j * 4);
    const uint32_t hoff16 = (uint32_t)(bl * HSTR + 512 + j * 2);

    float cst = 0.0f, hout = 0.0f;
    const size_t xw_dir = (size_t)dir * ((size_t)Tt * Bb * FOURH);

    for (int t = 0; t < Tt; t++) {
        const int tt = dir ? (Tt - 1 - t) : t;
        const int p = t & 1;
        // mbar[p] phase at step t (arrived at step t-1)
        const uint32_t wph = p ? ((uint32_t)(t >> 1) & 1u)
                               : (((uint32_t)(t >> 1) - 1u) & 1u);

        // xw prefetch before the wait — DRAM latency overlaps the sync
        const float* xwp = g_xw + xw_dir + ((size_t)tt * Bb + b) * FOURH;
        const float x0 = __ldg(xwp + j);
        const float x1 = __ldg(xwp + Hh + j);
        const float x2 = __ldg(xwp + 2 * Hh + j);
        const float x3 = __ldg(xwp + 3 * Hh + j);

        if (t > 0) mbar_wait_acq(sbase + (uint32_t)(p * 8), wph);

        // z = h @ U via tensor cores; 2 chains per tile
        float cA[2][4], cB[2][4];
#pragma unroll
        for (int i = 0; i < 2; i++)
#pragma unroll
            for (int q = 0; q < 4; q++) { cA[i][q] = 0.0f; cB[i][q] = 0.0f; }

        const uint32_t abase = hb + (uint32_t)(p * HBUFSZ) + rowoff;
#pragma unroll
        for (int ks = 0; ks < NKS; ks++) {
            uint32_t a[4];
            LDSM_X4(a[0], a[1], a[2], a[3], abase + (uint32_t)(32 * ks));
            if (ks & 1) {
                MMA16816(cB[0], a, breg[ks][0][0], breg[ks][0][1]);
                MMA16816(cB[1], a, breg[ks][1][0], breg[ks][1][1]);
            } else {
                MMA16816(cA[0], a, breg[ks][0][0], breg[ks][0][1]);
                MMA16816(cA[1], a, breg[ks][1][0], breg[ks][1][1]);
            }
        }
        *(float2*)&z_sm[nq][w * 16 + 2 * kq] =
            make_float2(cA[0][0] + cB[0][0], cA[0][1] + cB[0][1]);
        *(float2*)&z_sm[nq][w * 16 + 8 + 2 * kq] =
            make_float2(cA[1][0] + cB[1][0], cA[1][1] + cB[1][1]);
        __syncthreads();

        // gates: thread = unit ju x row bl
        const float a0 = z_sm[bl][ju]      + x0 + bz0;
        const float a1 = z_sm[bl][32 + ju] + x1 + bz1;
        const float a2 = z_sm[bl][64 + ju] + x2 + bz2;
        const float a3 = z_sm[bl][96 + ju] + x3 + bz3;
        {
            const float ig = sigmoid_f(a0), fg = sigmoid_f(a1);
            const float gg = tanh_f(a2),    og = sigmoid_f(a3);
            cst = fg * cst + ig * gg;
            hout = og * tanh_f(cst);
        }

        // publish h (bf16 hi/lo) into buffer p^1 of all 4 cluster CTAs
        {
            const unsigned short hh = bfu(hout);
            const unsigned short hl = bfu(hout - bff(hh));
            const uint32_t v32 = (uint32_t)hh | ((uint32_t)hl << 16);
            const uint32_t base = hb + (uint32_t)((p ^ 1) * HBUFSZ);
#pragma unroll
            for (int r = 0; r < 4; r++) {
                st_cluster_u32(base + hoff32, r, v32);
                st_cluster_u16(base + hoff16, r, hh);
            }
        }
        __syncthreads();           // all threads' stores issued + z_sm reusable
        if (tid < 4) mbar_arrive_rel(sbase + (uint32_t)((p ^ 1) * 8), tid);

        // out store in the shadow of the sync propagation
        out[((size_t)b * Tt + tt) * 256 + dir * Hh + j] = hout;
    }

    const size_t fin = (size_t)Bb * Tt * 256 + (size_t)dir * 2 * Bb * Hh;
    out[fin + (size_t)b * Hh + j]           = hout;
    out[fin + Bb * Hh + (size_t)b * Hh + j] = cst;

    CLUSTER_SYNC();   // keep smem alive until all peers stop DSMEM-writing
}

// ---------------- launch ----------------
extern "C" void kernel_launch(void* const* d_in, const int* in_sizes, int n_in,
                              void* d_out, int out_size) {
    const int*   tokens = (const int*)d_in[0];
    const float* emb    = (const float*)d_in[1];
    const float* Wfw    = (const float*)d_in[2];
    const float* Ufw    = (const float*)d_in[3];
    const float* bfw    = (const float*)d_in[4];
    const float* Wbw    = (const float*)d_in[5];
    const float* Ubw    = (const float*)d_in[6];
    const float* bbw    = (const float*)d_in[7];
    float* out = (float*)d_out;

    static bool attr_set = false;
    if (!attr_set) {
        cudaFuncSetAttribute(lstm_kernel, cudaFuncAttributeMaxDynamicSharedMemorySize,
                             (int)LSTM_SMEM);
        attr_set = true;
    }

    conv_emb<<<(Vv * Ee + 255) / 256, 256>>>(emb);
    conv_w<<<(2 * KP * FOURH + 255) / 256, 256>>>(Wfw, Wbw);
    proj_mma<<<dim3(4, 512, 2), 256>>>(tokens);
    lstm_kernel<<<128, 256, LSTM_SMEM>>>(Ufw, Ubw, bfw, bbw, out);
}

// round 15
// speedup vs baseline: 1.2510x; 1.0077x over previous
#include <cuda_runtime.h>
#include <cuda_bf16.h>
#include <cstdint>
#include <math.h>

#define Bb 128
#define Tt 512
#define Ee 256
#define Hh 128
#define FOURH 512
#define Vv 32000
#define KP 768

typedef unsigned long long u64t;
typedef __nv_bfloat16 bf16;

// ---------------- static scratch ----------------
__device__ float g_xw[(size_t)2 * Tt * Bb * FOURH];      // [dir][t*128+b][4H]
__device__ __align__(16) bf16 g_ehi[(size_t)Vv * Ee];
__device__ __align__(16) bf16 g_elo[(size_t)Vv * Ee];
__device__ __align__(16) bf16 g_Wt[2][KP][FOURH];        // [dir][k'][n]

// ---------------- helpers ----------------
__device__ __forceinline__ float sigmoid_f(float x) { return __fdividef(1.0f, 1.0f + __expf(-x)); }
__device__ __forceinline__ float tanh_f(float x)    { return __fdividef(2.0f, 1.0f + __expf(-2.0f * x)) - 1.0f; }
__device__ __forceinline__ uint32_t smem_u32(const void* p) {
    uint32_t a;
    asm("{ .reg .u64 t; cvta.to.shared.u64 t, %1; cvt.u32.u64 %0, t; }" : "=r"(a) : "l"(p));
    return a;
}
__device__ __forceinline__ void st_cluster_u32(uint32_t laddr, int rank, uint32_t v) {
    asm volatile(
        "{ .reg .b32 ra; mapa.shared::cluster.u32 ra, %0, %1; "
        "st.shared::cluster.b32 [ra], %2; }"
        :: "r"(laddr), "r"(rank), "r"(v) : "memory");
}
__device__ __forceinline__ void st_cluster_u16(uint32_t laddr, int rank, unsigned short v) {
    asm volatile(
        "{ .reg .b32 ra; mapa.shared::cluster.u32 ra, %0, %1; "
        "st.shared::cluster.b16 [ra], %2; }"
        :: "r"(laddr), "r"(rank), "h"(v) : "memory");
}
__device__ __forceinline__ void mbar_arrive_rel(uint32_t laddr, int rank) {
    asm volatile(
        "{ .reg .b32 ra; mapa.shared::cluster.u32 ra, %0, %1; "
        "mbarrier.arrive.release.cluster.shared::cluster.b64 _, [ra]; }"
        :: "r"(laddr), "r"(rank) : "memory");
}
__device__ __forceinline__ void mbar_wait_acq(uint32_t mb, uint32_t parity) {
    asm volatile(
        "{\n\t.reg .pred P1;\n\t"
        "WL_%=:\n\t"
        "mbarrier.try_wait.parity.acquire.cluster.shared::cta.b64 P1, [%0], %1, 0x989680;\n\t"
        "@P1 bra.uni WD_%=;\n\t"
        "bra.uni WL_%=;\n\t"
        "WD_%=:\n\t}" :: "r"(mb), "r"(parity) : "memory");
}
#define MBAR_INIT(a, n) \
    asm volatile("mbarrier.init.shared.b64 [%0], %1;" :: "r"(a), "r"((uint32_t)(n)) : "memory")
#define CLUSTER_SYNC() do { \
    asm volatile("barrier.cluster.arrive.aligned;" ::: "memory"); \
    asm volatile("barrier.cluster.wait.aligned;" ::: "memory"); \
} while (0)

#define LDSM_X4(r0, r1, r2, r3, addr) \
    asm volatile("ldmatrix.sync.aligned.m8n8.x4.shared.b16 {%0,%1,%2,%3}, [%4];" \
                 : "=r"(r0), "=r"(r1), "=r"(r2), "=r"(r3) : "r"(addr))
#define LDSM_X4T(r0, r1, r2, r3, addr) \
    asm volatile("ldmatrix.sync.aligned.m8n8.x4.trans.shared.b16 {%0,%1,%2,%3}, [%4];" \
                 : "=r"(r0), "=r"(r1), "=r"(r2), "=r"(r3) : "r"(addr))
#define MMA16816(c, a, b0, b1) \
    asm volatile("mma.sync.aligned.m16n8k16.row.col.f32.bf16.bf16.f32 " \
                 "{%0,%1,%2,%3}, {%4,%5,%6,%7}, {%8,%9}, {%0,%1,%2,%3};" \
                 : "+f"((c)[0]), "+f"((c)[1]), "+f"((c)[2]), "+f"((c)[3]) \
                 : "r"((a)[0]), "r"((a)[1]), "r"((a)[2]), "r"((a)[3]), "r"(b0), "r"(b1))

__device__ __forceinline__ unsigned short bfu(float x) {
    bf16 h = __float2bfloat16(x);
    return __bfloat16_as_ushort(h);
}
__device__ __forceinline__ float bff(unsigned short u) {
    return __bfloat162float(__ushort_as_bfloat16(u));
}

// ---------------- conversion kernels ----------------
__global__ void conv_emb(const float* __restrict__ emb) {
    size_t i = (size_t)blockIdx.x * 256 + threadIdx.x;
    if (i < (size_t)Vv * Ee) {
        float x = emb[i];
        bf16 h = __float2bfloat16(x);
        g_ehi[i] = h;
        g_elo[i] = __float2bfloat16(x - __bfloat162float(h));
    }
}
__global__ void conv_w(const float* __restrict__ Wfw, const float* __restrict__ Wbw) {
    int i = blockIdx.x * 256 + threadIdx.x;
    if (i < 2 * KP * FOURH) {
        int d  = i / (KP * FOURH);
        int r  = i % (KP * FOURH);
        int kp = r / FOURH, n = r % FOURH;
        const float* W = d ? Wbw : Wfw;
        float x = W[(size_t)(kp & 255) * FOURH + n];
        bf16 hv = __float2bfloat16(x);
        g_Wt[d][kp][n] = (kp >= 256 && kp < 512)
                             ? __float2bfloat16(x - __bfloat162float(hv)) : hv;
    }
}

// ---------------- mma.sync projection GEMM (unchanged) ----------------
#define ASTR 40
#define BSTR 136

__global__ __launch_bounds__(256)
void proj_mma(const int* __restrict__ tokens) {
    __shared__ __align__(16) bf16 A_sm[128 * ASTR];
    __shared__ __align__(16) bf16 B_sm[32 * BSTR];
    __shared__ int tok[128];

    const int tid = threadIdx.x;
    const int wid = tid >> 5, lane = tid & 31;
    const int wm = wid & 3, wn = wid >> 2;
    const int n0 = blockIdx.x * 128;
    const int m0 = blockIdx.y * 128;
    const int dir = blockIdx.z;

    if (tid < 128) {
        int row = m0 + tid;
        tok[tid] = tokens[(row & 127) * Tt + (row >> 7)];
    }
    const uint32_t sbA = smem_u32(A_sm);
    const uint32_t sbB = smem_u32(B_sm);

    float c[2][8][4];
#pragma unroll
    for (int i = 0; i < 2; i++)
#pragma unroll
        for (int j = 0; j < 8; j++)
#pragma unroll
            for (int q = 0; q < 4; q++) c[i][j][q] = 0.0f;

    __syncthreads();

    for (int kt = 0; kt < 24; kt++) {
        const int kp0 = kt * 32;
        const bf16* __restrict__ Asrc = (kp0 < 512) ? g_ehi : g_elo;
        const int kb = kp0 & 255;

        uint4 av[2], bv[2];
#pragma unroll
        for (int u = 0; u < 2; u++) {
            const int q = tid + u * 256;
            const int arow = q >> 2, ac8 = q & 3;
            av[u] = *(const uint4*)(Asrc + (size_t)tok[arow] * Ee + kb + ac8 * 8);
            const int brow = q >> 4, bn8 = q & 15;
            bv[u] = *(const uint4*)(&g_Wt[dir][kp0 + brow][n0 + bn8 * 8]);
        }
        __syncthreads();
#pragma unroll
        for (int u = 0; u < 2; u++) {
            const int q = tid + u * 256;
            const int arow = q >> 2, ac8 = q & 3;
            *(uint4*)(A_sm + arow * ASTR + ac8 * 8) = av[u];
            const int brow = q >> 4, bn8 = q & 15;
            *(uint4*)(B_sm + brow * BSTR + bn8 * 8) = bv[u];
        }
        __syncthreads();

#pragma unroll
        for (int ks = 0; ks < 2; ks++) {
            uint32_t a[2][4];
#pragma unroll
            for (int i = 0; i < 2; i++) {
                const int m = wm * 32 + i * 16 + (lane & 7) + ((lane >> 3) & 1) * 8;
                const int kc = ks * 16 + (lane >> 4) * 8;
                LDSM_X4(a[i][0], a[i][1], a[i][2], a[i][3],
                        sbA + (uint32_t)(m * ASTR + kc) * 2);
            }
            uint32_t b[4][4];
#pragma unroll
            for (int j2 = 0; j2 < 4; j2++) {
                const int k = ks * 16 + (lane & 7) + ((lane >> 3) & 1) * 8;
                const int n = wn * 64 + j2 * 16 + (lane >> 4) * 8;
                LDSM_X4T(b[j2][0], b[j2][1], b[j2][2], b[j2][3],
                         sbB + (uint32_t)(k * BSTR + n) * 2);
            }
#pragma unroll
            for (int i = 0; i < 2; i++)
#pragma unroll
                for (int j = 0; j < 8; j++)
                    MMA16816(c[i][j], a[i], b[j >> 1][(j & 1) * 2], b[j >> 1][(j & 1) * 2 + 1]);
        }
    }

    const int g = lane >> 2, t2 = (lane & 3) * 2;
    float* const base = g_xw + (size_t)dir * Tt * Bb * FOURH;
#pragma unroll
    for (int i = 0; i < 2; i++) {
        const int mrow = m0 + wm * 32 + i * 16 + g;
#pragma unroll
        for (int j = 0; j < 8; j++) {
            const int col = n0 + wn * 64 + j * 8 + t2;
            float* d0 = base + (size_t)mrow * FOURH + col;
            d0[0] = c[i][j][0]; d0[1] = c[i][j][1];
            float* d1 = d0 + 8 * FOURH;
            d1[0] = c[i][j][2]; d1[1] = c[i][j][3];
        }
    }
}

// ---------------- persistent LSTM: R12 structure + mbarrier sync ----------------
// 128 CTAs, cluster(4) = one (dir,btile). CTA: 8 batch rows x 32 units.
// Per step: z = h_pad[16,384] @ Ureg[384,128] via mma.sync, U in registers.
// h via DSMEM; per-parity mbarriers (count=4) replace barrier.cluster.
#define HSTR 784              // A row stride bytes (768 data + 16 pad)
#define NKS 24                // K' = 384 -> 24 k16 steps
#define HBUFSZ (16 * HSTR)
#define ZOFF   64
#define HOFF   (ZOFF + 8 * 132 * 4)          // 4288
#define LSTM_SMEM (HOFF + 2 * HBUFSZ)        // 29376

__global__ __launch_bounds__(256, 1) __cluster_dims__(4, 1, 1)
void lstm_kernel(const float* __restrict__ Ufw, const float* __restrict__ Ubw,
                 const float* __restrict__ bfw, const float* __restrict__ bbw,
                 float* __restrict__ out) {
    extern __shared__ char sm[];
    float (*z_sm)[132] = (float(*)[132])(sm + ZOFF);
    const uint32_t sbase = smem_u32(sm);
    const uint32_t hb = sbase + HOFF;

    const int bx = blockIdx.x;
    const int dir = bx >> 6, id = bx & 63;
    const int btile = id >> 2, utile = id & 3;
    const int tid = threadIdx.x;
    const int w = tid >> 5, lane = tid & 31;
    const int kq = lane & 3, nq = lane >> 2;
    const int ju = tid >> 3, bl = tid & 7;
    const int j = utile * 32 + ju;          // global unit 0..127
    const int b = btile * 8 + bl;           // global batch row

    const float* __restrict__ U    = dir ? Ubw : Ufw;
    const float* __restrict__ bias = dir ? bbw : bfw;

    // ---- U fragments in registers ----
    uint32_t breg[NKS][2][2];
#pragma unroll
    for (int tile = 0; tile < 2; tile++) {
        const int nloc = w * 16 + tile * 8 + nq;
        const int gcol = (nloc >> 5) * Hh + utile * 32 + (nloc & 31);
#pragma unroll
        for (int ks = 0; ks < 16; ks++) {      // (hhi,hlo) x dup(Uhi)
            const int u0 = 8 * ks + kq;
            const unsigned short h0 = bfu(U[(size_t)u0 * FOURH + gcol]);
            const unsigned short h1 = bfu(U[(size_t)(u0 + 4) * FOURH + gcol]);
            breg[ks][tile][0] = (uint32_t)h0 | ((uint32_t)h0 << 16);
            breg[ks][tile][1] = (uint32_t)h1 | ((uint32_t)h1 << 16);
        }
#pragma unroll
        for (int ks = 16; ks < NKS; ks++) {    // hhi x Ulo
            const int u0 = 16 * (ks - 16) + 2 * kq;
#pragma unroll
            for (int rr = 0; rr < 2; rr++) {
                const int ua = u0 + rr * 8, ub = ua + 1;
                float va = U[(size_t)ua * FOURH + gcol];
                float vb = U[(size_t)ub * FOURH + gcol];
                unsigned short la = bfu(va - bff(bfu(va)));
                unsigned short lb = bfu(vb - bff(bfu(vb)));
                breg[ks][tile][rr] = (uint32_t)la | ((uint32_t)lb << 16);
            }
        }
    }

    // zero both h buffers; init 2 per-parity mbarriers (count=4)
    for (int q = tid; q < (int)(2 * HBUFSZ / 4); q += 256)
        ((uint32_t*)(sm + HOFF))[q] = 0u;
    if (tid == 0) { MBAR_INIT(sbase, 4); MBAR_INIT(sbase + 8, 4); }

    const float bz0 = bias[j];
    const float bz1 = bias[Hh + j];
    const float bz2 = bias[2 * Hh + j];
    const float bz3 = bias[3 * Hh + j];

    __syncthreads();
    CLUSTER_SYNC();   // peers' mbars + zeroed buffers visible

    const int arow = (lane & 7) + ((lane >> 3) & 1) * 8;
    const uint32_t rowoff = (uint32_t)(arow * HSTR + (lane >> 4) * 16);
    const uint32_t hoff32 = (uint32_t)(bl * HSTR + j * 4);
    const uint32_t hoff16 = (uint32_t)(bl * HSTR + 512 + j * 2);

    float cst = 0.0f, hout = 0.0f;
    const size_t xw_dir = (size_t)dir * ((size_t)Tt * Bb * FOURH);

    for (int t = 0; t < Tt; t++) {
        const int tt = dir ? (Tt - 1 - t) : t;
        const int p = t & 1;
        // mbar[p] phase at step t (arrived at step t-1)
        const uint32_t wph = p ? ((uint32_t)(t >> 1) & 1u)
                               : (((uint32_t)(t >> 1) - 1u) & 1u);

        // xw prefetch before the wait — DRAM latency overlaps the sync
        const float* xwp = g_xw + xw_dir + ((size_t)tt * Bb + b) * FOURH;
        const float x0 = __ldg(xwp + j);
        const float x1 = __ldg(xwp + Hh + j);
        const float x2 = __ldg(xwp + 2 * Hh + j);
        const float x3 = __ldg(xwp + 3 * Hh + j);

        if (t > 0) mbar_wait_acq(sbase + (uint32_t)(p * 8), wph);

        // z = h @ U via tensor cores; 2 chains per tile
        float cA[2][4], cB[2][4];
#pragma unroll
        for (int i = 0; i < 2; i++)
#pragma unroll
            for (int q = 0; q < 4; q++) { cA[i][q] = 0.0f; cB[i][q] = 0.0f; }

        const uint32_t abase = hb + (uint32_t)(p * HBUFSZ) + rowoff;
#pragma unroll
        for (int ks = 0; ks < NKS; ks++) {
            uint32_t a[4];
            LDSM_X4(a[0], a[1], a[2], a[3], abase + (uint32_t)(32 * ks));
            if (ks & 1) {
                MMA16816(cB[0], a, breg[ks][0][0], breg[ks][0][1]);
                MMA16816(cB[1], a, breg[ks][1][0], breg[ks][1][1]);
            } else {
                MMA16816(cA[0], a, breg[ks][0][0], breg[ks][0][1]);
                MMA16816(cA[1], a, breg[ks][1][0], breg[ks][1][1]);
            }
        }
        *(float2*)&z_sm[nq][w * 16 + 2 * kq] =
            make_float2(cA[0][0] + cB[0][0], cA[0][1] + cB[0][1]);
        *(float2*)&z_sm[nq][w * 16 + 8 + 2 * kq] =
            make_float2(cA[1][0] + cB[1][0], cA[1][1] + cB[1][1]);
        __syncthreads();

        // gates: thread = unit ju x row bl
        const float a0 = z_sm[bl][ju]      + x0 + bz0;
        const float a1 = z_sm[bl][32 + ju] + x1 + bz1;
        const float a2 = z_sm[bl][64 + ju] + x2 + bz2;
        const float a3 = z_sm[bl][96 + ju] + x3 + bz3;
        {
            const float ig = sigmoid_f(a0), fg = sigmoid_f(a1);
            const float gg = tanh_f(a2),    og = sigmoid_f(a3);
            cst = fg * cst + ig * gg;
            hout = og * tanh_f(cst);
        }

        // publish h (bf16 hi/lo) into buffer p^1 of all 4 cluster CTAs
        {
            const unsigned short hh = bfu(hout);
            const unsigned short hl = bfu(hout - bff(hh));
            const uint32_t v32 = (uint32_t)hh | ((uint32_t)hl << 16);
            const uint32_t base = hb + (uint32_t)((p ^ 1) * HBUFSZ);
#pragma unroll
            for (int r = 0; r < 4; r++) {
                st_cluster_u32(base + hoff32, r, v32);
                st_cluster_u16(base + hoff16, r, hh);
            }
        }
        __syncthreads();           // all threads' stores issued + z_sm reusable
        if (tid < 4) mbar_arrive_rel(sbase + (uint32_t)((p ^ 1) * 8), tid);

        // out store in the shadow of the sync propagation
        out[((size_t)b * Tt + tt) * 256 + dir * Hh + j] = hout;
    }

    const size_t fin = (size_t)Bb * Tt * 256 + (size_t)dir * 2 * Bb * Hh;
    out[fin + (size_t)b * Hh + j]           = hout;
    out[fin + Bb * Hh + (size_t)b * Hh + j] = cst;

    CLUSTER_SYNC();   // keep smem alive until all peers stop DSMEM-writing
}

// ---------------- launch ----------------
extern "C" void kernel_launch(void* const* d_in, const int* in_sizes, int n_in,
                              void* d_out, int out_size) {
    const int*   tokens = (const int*)d_in[0];
    const float* emb    = (const float*)d_in[1];
    const float* Wfw    = (const float*)d_in[2];
    const float* Ufw    = (const float*)d_in[3];
    const float* bfw    = (const float*)d_in[4];
    const float* Wbw    = (const float*)d_in[5];
    const float* Ubw    = (const float*)d_in[6];
    const float* bbw    = (const float*)d_in[7];
    float* out = (float*)d_out;

    static bool attr_set = false;
    if (!attr_set) {
        cudaFuncSetAttribute(lstm_kernel, cudaFuncAttributeMaxDynamicSharedMemorySize,
                             (int)LSTM_SMEM);
        attr_set = true;
    }

    conv_emb<<<(Vv * Ee + 255) / 256, 256>>>(emb);
    conv_w<<<(2 * KP * FOURH + 255) / 256, 256>>>(Wfw, Wbw);
    proj_mma<<<dim3(4, 512, 2), 256>>>(tokens);
    lstm_kernel<<<128, 256, LSTM_SMEM>>>(Ufw, Ubw, bfw, bbw, out);
}